// round 9
// baseline (speedup 1.0000x reference)
#include <cuda_runtime.h>
#include <cstdint>

#define NC 16
#define HW (512*512)
#define NB 8
#define M (NB*HW)
#define HBLK 256
#define WT 32                   // pixels per warp-tile
#define NWT (M / WT)            // 65536 warp-tiles
#define GRID 740
#define NWARP (GRID * 8)        // 5920

__device__ double       g_acc[2];
__device__ unsigned int g_done;
__device__ unsigned int g_hdone;
__device__ float        g_part[HBLK * NC];
__device__ float        g_cc[NC];

__device__ __forceinline__ int iget(const int4& v, int j) {
    return j == 0 ? v.x : j == 1 ? v.y : j == 2 ? v.z : v.w;
}
__device__ __forceinline__ void cp16(uint32_t dst, const void* src) {
    asm volatile("cp.async.cg.shared.global [%0], [%1], 16;" :: "r"(dst), "l"(src));
}

// ------------------------------------------------ histogram + last-block reduce
__global__ void __launch_bounds__(256) k_hist(const int4* __restrict__ labels,
                                              const float* __restrict__ cums) {
    if (threadIdx.x == 0) cudaTriggerProgrammaticLaunchCompletion();
    int lane = threadIdx.x & 31;
    int w    = threadIdx.x >> 5;
    int cnt = 0;
    int idx    = blockIdx.x * blockDim.x + threadIdx.x;
    int stride = gridDim.x * blockDim.x;
    for (int i = idx; i < M / 4; i += stride) {
        int4 lb = labels[i];
        #pragma unroll
        for (int k = 0; k < 4; k++) {
            int lab = iget(lb, k);
            #pragma unroll
            for (int c = 0; c < NC; c++) {
                unsigned mb = __ballot_sync(0xFFFFFFFFu, lab == c);
                if (lane == c) cnt += __popc(mb);
            }
        }
    }
    __shared__ int sm[8 * NC];
    if (lane < NC) sm[w * NC + lane] = cnt;
    __syncthreads();
    int t = threadIdx.x;
    if (t < NC) {
        int tot = 0;
        #pragma unroll
        for (int i = 0; i < 8; i++) tot += sm[i * NC + t];
        g_part[blockIdx.x * NC + t] = (float)tot;
    }
    __shared__ bool is_last;
    __threadfence();
    __syncthreads();
    if (t == 0) is_last = (atomicAdd(&g_hdone, 1u) == HBLK - 1);
    __syncthreads();
    if (is_last) {
        __shared__ float sr[256];
        int c  = t & 15;
        int r0 = t >> 4;
        float sum = 0.f;
        #pragma unroll
        for (int k = 0; k < HBLK / 16; k++)
            sum += g_part[(r0 + k * 16) * NC + c];
        sr[t] = sum;
        __syncthreads();
        if (t < NC) {
            float tot = 0.f;
            #pragma unroll
            for (int r = 0; r < 16; r++) tot += sr[r * NC + t];
            g_cc[t] = fmaxf(cums[t] + tot, 1.0f);
        }
        if (t == 0) g_hdone = 0u;
        __threadfence();
    }
}

// ------------------------------------------------ per-warp pipelined main
__global__ void __launch_bounds__(256) k_main(const float* __restrict__ cls,
                                              const int*   __restrict__ labels,
                                              float*       __restrict__ out) {
    __shared__ float s_l[8][2][NC][WT];   // 32 KB: per-warp double-buffered tiles
    __shared__ int   s_lab[8][2][WT];     //  2 KB
    __shared__ float smit[NC * NC];       //  1 KB transposed: smit[c*16+lab]
    __shared__ float rn[8], rm[8];

    int tid  = threadIdx.x;
    int lane = tid & 31;
    int wrp  = tid >> 5;

    uint32_t sl_base = (uint32_t)__cvta_generic_to_shared(&s_l[wrp][0][0][0]);
    uint32_t sb_base = (uint32_t)__cvta_generic_to_shared(&s_lab[wrp][0][0]);
    int ch0  = lane >> 3;                 // 0..3
    int part = lane & 7;                  // 0..7  (part*16B within a 128B channel row)

    // per-warp tile load: 32 px x 16 ch = 2 KB + 128 B labels, own commit group
    auto issue = [&](int tile, int bi) {
        int b  = tile >> 13;                          // (tile*32) >> 18
        int hw = (tile & 8191) << 5;                  // (tile*32) & (HW-1)
        const float* src = cls + (size_t)b * (NC * HW) + hw;
        uint32_t dst = sl_base + (uint32_t)(bi * (NC * WT * 4));
        #pragma unroll
        for (int k = 0; k < 4; k++) {
            int ch = ch0 + k * 4;
            cp16(dst + (uint32_t)(ch * (WT * 4) + part * 16),
                 src + (size_t)ch * HW + part * 4);
        }
        if (lane < 8)
            cp16(sb_base + (uint32_t)(bi * (WT * 4) + lane * 16),
                 labels + tile * WT + lane * 4);
        asm volatile("cp.async.commit_group;");
    };

    int g = blockIdx.x * 8 + wrp;         // global warp id
    issue(g, 0);                          // prefetch overlaps k_hist via PDL

    cudaGridDependencySynchronize();      // wait for k_hist's g_cc
    {
        int labi = tid & 15;
        int ci   = tid >> 4;
        float ratio = g_cc[ci] / g_cc[labi];
        smit[tid] = (ratio < 1.0f) ? __powf(ratio, 0.8f) : 1.0f;
    }
    __syncthreads();                      // smit visible to all warps

    float nll = 0.f, msk = 0.f;
    int buf = 0;
    for (int t = g; t < NWT; t += NWARP) {
        int nxt = t + NWARP;
        if (nxt < NWT) {
            issue(nxt, buf ^ 1);
            asm volatile("cp.async.wait_group 1;");
        } else {
            asm volatile("cp.async.wait_group 0;");
        }
        __syncwarp();                     // own-warp tile visible

        int lab = s_lab[wrp][buf][lane];

        float e[NC];
        float s = 0.f;
        #pragma unroll
        for (int c = 0; c < NC; c++) {
            float ec = __expf(s_l[wrp][buf][c][lane]);   // conflict-free LDS
            e[c] = ec;
            s += ec;
        }
        float l_lab = s_l[wrp][buf][lab][lane];          // dynamic LDS, bank=lane
        float selfE = __expf(l_lab);
        float inv = __fdividef(1.0f, fmaxf(selfE, 0.01f * s));

        float sum2 = 0.f;
        #pragma unroll
        for (int c = 0; c < NC; c++) {
            float tt = fmaxf(e[c] * inv, 1.0f);
            float es = e[c] * smit[(c << 4) + lab];
            sum2 = fmaf(es, tt * tt, sum2);
        }

        if (lab != 0) {
            nll += __logf(sum2) - l_lab;                 // ln(selfE) == l_lab
            msk += 1.f;
        }
        __syncwarp();                     // done reading buf before refill
        buf ^= 1;
    }

    // block reduction + finalize
    #pragma unroll
    for (int o = 16; o > 0; o >>= 1) {
        nll += __shfl_down_sync(0xFFFFFFFFu, nll, o);
        msk += __shfl_down_sync(0xFFFFFFFFu, msk, o);
    }
    if (lane == 0) { rn[wrp] = nll; rm[wrp] = msk; }
    __syncthreads();
    if (tid == 0) {
        float a = 0.f, bs = 0.f;
        #pragma unroll
        for (int i = 0; i < 8; i++) { a += rn[i]; bs += rm[i]; }
        atomicAdd(&g_acc[0], (double)a);
        atomicAdd(&g_acc[1], (double)bs);
        __threadfence();
        unsigned v = atomicAdd(&g_done, 1u);
        if (v == GRID - 1) {              // last block: finalize + reset
            __threadfence();
            out[0] = (float)(g_acc[0] / g_acc[1]);
            g_acc[0] = 0.0;
            g_acc[1] = 0.0;
            g_done   = 0u;
        }
    }
}

extern "C" void kernel_launch(void* const* d_in, const int* in_sizes, int n_in,
                              void* d_out, int out_size) {
    const float* cls    = (const float*)d_in[0];
    const int*   labels = (const int*)  d_in[1];
    const float* cums   = (const float*)d_in[2];
    float* out = (float*)d_out;

    k_hist<<<HBLK, 256>>>((const int4*)labels, cums);

    // PDL launch: k_main may start while k_hist runs; it prefetches, then
    // cudaGridDependencySynchronize() gates the g_cc read.
    cudaLaunchConfig_t cfg = {};
    cfg.gridDim  = dim3(GRID, 1, 1);
    cfg.blockDim = dim3(256, 1, 1);
    cfg.dynamicSmemBytes = 0;
    cfg.stream = 0;
    cudaLaunchAttribute at[1];
    at[0].id = cudaLaunchAttributeProgrammaticStreamSerialization;
    at[0].val.programmaticStreamSerializationAllowed = 1;
    cfg.attrs = at;
    cfg.numAttrs = 1;
    cudaLaunchKernelEx(&cfg, k_main, cls, labels, out);
}

// round 10
// speedup vs baseline: 1.0007x; 1.0007x over previous
#include <cuda_runtime.h>
#include <cstdint>

#define NC 16
#define HW (512*512)
#define NB 8
#define M (NB*HW)
#define TPX 256
#define NTILES (M / TPX)       // 8192
#define GRID 740               // 148 SMs * 5 CTAs (exact residency, spin-safe)

__device__ double       g_acc[2];
__device__ unsigned int g_done;
__device__ unsigned int g_hdone;
__device__ unsigned int g_ready;           // plain-store flag, volatile-polled
__device__ unsigned int g_tile = GRID;     // stealing cursor; reset at end
__device__ float        g_part[GRID * NC];
__device__ float        g_cc[NC];
__device__ float        g_mit[NC * NC];    // transposed: g_mit[c*16+lab]

__device__ __forceinline__ int iget(const int4& v, int j) {
    return j == 0 ? v.x : j == 1 ? v.y : j == 2 ? v.z : v.w;
}
__device__ __forceinline__ void cp16(uint32_t dst, const void* src) {
    asm volatile("cp.async.cg.shared.global [%0], [%1], 16;" :: "r"(dst), "l"(src));
}

__global__ void __launch_bounds__(256) k_all(const float* __restrict__ cls,
                                             const int*   __restrict__ labels,
                                             const float* __restrict__ cums,
                                             float*       __restrict__ out) {
    __shared__ float s_l[2][NC][TPX];     // 32 KB logit tiles
    __shared__ int   s_lab[2][TPX];       //  2 KB
    __shared__ float smit[NC * NC];
    __shared__ float sr[256];
    __shared__ int   shist[8 * NC];
    __shared__ int   s_next[2];
    __shared__ bool  s_flag;
    __shared__ float rn[8], rm[8];

    int tid  = threadIdx.x;
    int lane = tid & 31;
    int wrp  = tid >> 5;

    uint32_t s_l_base   = (uint32_t)__cvta_generic_to_shared(&s_l[0][0][0]);
    uint32_t s_lab_base = (uint32_t)__cvta_generic_to_shared(&s_lab[0][0]);
    int ch0  = tid >> 6;
    int part = tid & 63;

    auto issue = [&](int tile, int bi) {
        int b  = tile >> 10;                       // (tile*256) >> 18
        int hw = (tile & 1023) << 8;
        const float* src = cls + (size_t)b * (NC * HW) + hw + (size_t)ch0 * HW + part * 4;
        uint32_t dst = s_l_base + (uint32_t)(((bi * NC + ch0) * TPX + part * 4) * 4);
        #pragma unroll
        for (int k = 0; k < 4; k++)
            cp16(dst + (uint32_t)k * (4 * TPX * 4), src + (size_t)k * 4 * HW);
        if (tid < 64)
            cp16(s_lab_base + (uint32_t)((bi * TPX + tid * 4) * 4),
                 labels + tile * TPX + tid * 4);
        asm volatile("cp.async.commit_group;");
    };

    // prefetch first tile; it streams while we histogram
    issue(blockIdx.x, 0);

    // ---------------- histogram phase (all blocks participate) ---------------
    {
        int cnt = 0;
        const int4* lab4 = (const int4*)labels;
        int base = blockIdx.x * 256 + tid;
        #pragma unroll
        for (int k = 0; k < 3; k++) {                    // ceil(524288/189440)=3
            int i = base + k * (GRID * 256);
            int4 lb = (i < M / 4) ? lab4[i] : make_int4(-1, -1, -1, -1);
            #pragma unroll
            for (int j = 0; j < 4; j++) {
                int lab = iget(lb, j);
                #pragma unroll
                for (int c = 0; c < NC; c++) {
                    unsigned mb = __ballot_sync(0xFFFFFFFFu, lab == c);
                    if (lane == c) cnt += __popc(mb);
                }
            }
        }
        if (lane < NC) shist[wrp * NC + lane] = cnt;
        __syncthreads();
        if (tid < NC) {
            int tot = 0;
            #pragma unroll
            for (int i = 0; i < 8; i++) tot += shist[i * NC + tid];
            g_part[blockIdx.x * NC + tid] = (float)tot;
        }
        __threadfence();
        __syncthreads();
        if (tid == 0) s_flag = (atomicAdd(&g_hdone, 1u) == GRID - 1);
        __syncthreads();
        if (s_flag) {                 // last block: reduce partials, build table
            int c  = tid & 15;
            int r0 = tid >> 4;
            float sum = 0.f;
            for (int k = 0; k < (GRID + 15) / 16; k++) {
                int r = r0 + k * 16;
                if (r < GRID) sum += g_part[r * NC + c];
            }
            sr[tid] = sum;
            __syncthreads();
            if (tid < NC) {
                float tot = 0.f;
                #pragma unroll
                for (int r = 0; r < 16; r++) tot += sr[r * NC + tid];
                g_cc[tid] = fmaxf(cums[tid] + tot, 1.0f);
            }
            __syncthreads();
            {
                int labi = tid & 15;
                int ci   = tid >> 4;
                float ratio = g_cc[ci] / g_cc[labi];
                g_mit[tid] = (ratio < 1.0f) ? __powf(ratio, 0.8f) : 1.0f;
            }
            __threadfence();
            __syncthreads();
            if (tid == 0) {
                g_hdone = 0u;                       // reset for next replay
                __threadfence();
                *(volatile unsigned int*)&g_ready = 1u;   // plain store, no atomic
            }
        }
    }

    // cheap poll: plain volatile load, no L2-atomic serialization
    if (tid == 0) {
        while (*(volatile unsigned int*)&g_ready == 0u) __nanosleep(128);
    }
    __syncthreads();
    smit[tid] = __ldcg(&g_mit[tid]);                // L2 read, writer fenced
    if (tid == 0) s_next[0] = atomicAdd(&g_tile, 1);

    // ---------------- main loop (R8 structure, proven 30us) ------------------
    float nll = 0.f, msk = 0.f;
    int t_cur = blockIdx.x;
    int buf = 0;
    while (t_cur < NTILES) {
        __syncthreads();                   // s_next[buf] + smit visible
        int t_nxt = s_next[buf];
        if (t_nxt < NTILES) {
            issue(t_nxt, buf ^ 1);
            if (tid == 0) s_next[buf ^ 1] = atomicAdd(&g_tile, 1);
            asm volatile("cp.async.wait_group 1;");
        } else {
            asm volatile("cp.async.wait_group 0;");
        }
        __syncthreads();                   // buf data ready

        int lab = s_lab[buf][tid];

        float e[NC];
        float s = 0.f;
        #pragma unroll
        for (int c = 0; c < NC; c++) {
            float ec = __expf(s_l[buf][c][tid]);   // conflict-free LDS
            e[c] = ec;
            s += ec;
        }
        float l_lab = s_l[buf][lab][tid];          // dynamic LDS, bank = tid%32
        float selfE = __expf(l_lab);
        float inv = __fdividef(1.0f, fmaxf(selfE, 0.01f * s));

        float sum2 = 0.f;
        #pragma unroll
        for (int c = 0; c < NC; c++) {
            float tt = fmaxf(e[c] * inv, 1.0f);
            float es = e[c] * smit[(c << 4) + lab];
            sum2 = fmaf(es, tt * tt, sum2);
        }

        if (lab != 0) {
            nll += __logf(sum2) - l_lab;           // ln(selfE) == l_lab exactly
            msk += 1.f;
        }
        t_cur = t_nxt;
        buf ^= 1;
    }

    // ---------------- reduction + finalize + state reset ---------------------
    #pragma unroll
    for (int o = 16; o > 0; o >>= 1) {
        nll += __shfl_down_sync(0xFFFFFFFFu, nll, o);
        msk += __shfl_down_sync(0xFFFFFFFFu, msk, o);
    }
    if (lane == 0) { rn[wrp] = nll; rm[wrp] = msk; }
    __syncthreads();
    if (tid == 0) {
        float a = 0.f, bs = 0.f;
        #pragma unroll
        for (int i = 0; i < 8; i++) { a += rn[i]; bs += rm[i]; }
        atomicAdd(&g_acc[0], (double)a);
        atomicAdd(&g_acc[1], (double)bs);
        __threadfence();
        unsigned v = atomicAdd(&g_done, 1u);
        if (v == GRID - 1) {               // last block: finalize + full reset
            __threadfence();
            out[0] = (float)(g_acc[0] / g_acc[1]);
            g_acc[0] = 0.0;
            g_acc[1] = 0.0;
            g_done   = 0u;
            g_ready  = 0u;
            g_tile   = GRID;
        }
    }
}

extern "C" void kernel_launch(void* const* d_in, const int* in_sizes, int n_in,
                              void* d_out, int out_size) {
    const float* cls    = (const float*)d_in[0];
    const int*   labels = (const int*)  d_in[1];
    const float* cums   = (const float*)d_in[2];
    float* out = (float*)d_out;

    k_all<<<GRID, 256>>>(cls, labels, cums, out);
}